// round 3
// baseline (speedup 1.0000x reference)
#include <cuda_runtime.h>
#include <cuda_bf16.h>
#include <cstdint>

#define BB 2
#define EM 512
#define NH 8
#define DH 64
#define TT 2048
#define EPS 1e-5f

// ---------------- scratch (no allocation allowed) ----------------
__device__ float g_wn[4][EM * EM];            // standardized weights
__device__ float g_p[3][BB * EM * TT];        // projected q,k,v (LN in place)
__device__ float g_attn[BB * EM * TT];        // attention output

// ---------------- kernel 1: weight standardization ----------------
__global__ void std_weights(const float* __restrict__ W, float* __restrict__ Wn) {
    __shared__ float ssum[256], ssq[256];
    int row = blockIdx.x;
    const float* wr = W + row * EM;
    float s = 0.f, s2 = 0.f;
    for (int i = threadIdx.x; i < EM; i += 256) { float v = wr[i]; s += v; s2 += v * v; }
    ssum[threadIdx.x] = s; ssq[threadIdx.x] = s2;
    __syncthreads();
    for (int o = 128; o > 0; o >>= 1) {
        if (threadIdx.x < o) { ssum[threadIdx.x] += ssum[threadIdx.x + o]; ssq[threadIdx.x] += ssq[threadIdx.x + o]; }
        __syncthreads();
    }
    float mu  = ssum[0] * (1.f / EM);
    float var = ssq[0] * (1.f / EM) - mu * mu;
    float r   = rsqrtf(var + EPS);
    for (int i = threadIdx.x; i < EM; i += 256) Wn[row * EM + i] = (wr[i] - mu) * r;
}

// ---------------- kernel 2: projection SGEMM ----------------
// Y[b,o,t] = mask[b,t] * sum_i Wn[o,i] X[b,i,t] + bias[o]
// grid (T/64, EM/64, B), block 256, 4x4 micro-tiles
__global__ void __launch_bounds__(256) proj64(
    const float* __restrict__ Wn, const float* __restrict__ X,
    const float* __restrict__ bias, const int* __restrict__ mask,
    float* __restrict__ Y)
{
    __shared__ float As[16][68];   // As[k][m]
    __shared__ float Bs[16][64];   // Bs[k][t]
    int b  = blockIdx.z;
    int m0 = blockIdx.y * 64, t0 = blockIdx.x * 64;
    int tid = threadIdx.x;
    int tx = tid & 15, ty = tid >> 4;
    const float* Xb = X + (size_t)b * EM * TT;
    float acc[4][4] = {};

    for (int k0 = 0; k0 < EM; k0 += 16) {
        {   // A tile: W[m0+m][k0 .. k0+16)
            int m = tid >> 2, k4 = (tid & 3) * 4;
            float4 w = *(const float4*)(Wn + (size_t)(m0 + m) * EM + k0 + k4);
            As[k4 + 0][m] = w.x; As[k4 + 1][m] = w.y;
            As[k4 + 2][m] = w.z; As[k4 + 3][m] = w.w;
        }
        {   // B tile: X[k0+kk][t0 .. t0+64)
            int kk = tid >> 4, t4 = (tid & 15) * 4;
            *(float4*)&Bs[kk][t4] = *(const float4*)(Xb + (size_t)(k0 + kk) * TT + t0 + t4);
        }
        __syncthreads();
#pragma unroll
        for (int k = 0; k < 16; k++) {
            float4 a  = *(const float4*)&As[k][ty * 4];
            float4 bv = *(const float4*)&Bs[k][tx * 4];
            float av[4] = {a.x, a.y, a.z, a.w};
            float bw[4] = {bv.x, bv.y, bv.z, bv.w};
#pragma unroll
            for (int i = 0; i < 4; i++)
#pragma unroll
                for (int j = 0; j < 4; j++) acc[i][j] += av[i] * bw[j];
        }
        __syncthreads();
    }
#pragma unroll
    for (int i = 0; i < 4; i++) {
        int m = m0 + ty * 4 + i;
        float bi = bias[m];
#pragma unroll
        for (int j = 0; j < 4; j++) {
            int t = t0 + tx * 4 + j;
            float mk = (float)mask[b * TT + t];
            Y[(size_t)b * EM * TT + (size_t)m * TT + t] = acc[i][j] * mk + bi;
        }
    }
}

// ---------------- kernel 3: per-head LayerNorm over DH ----------------
// grid (T/256, NH, B), block 256; normalize x[b, h*64+d, t] over d
__global__ void ln_head_k(float* __restrict__ X,
                          const float* __restrict__ g, const float* __restrict__ be)
{
    int t = blockIdx.x * 256 + threadIdx.x;
    int h = blockIdx.y, b = blockIdx.z;
    float* base = X + (size_t)b * EM * TT + (size_t)h * DH * TT + t;
    float s = 0.f, s2 = 0.f;
    float v[DH];
#pragma unroll
    for (int d = 0; d < DH; d++) { v[d] = base[(size_t)d * TT]; s += v[d]; s2 += v[d] * v[d]; }
    float mu  = s * (1.f / DH);
    float var = s2 * (1.f / DH) - mu * mu;
    float r   = rsqrtf(var + EPS);
#pragma unroll
    for (int d = 0; d < DH; d++) base[(size_t)d * TT] = (v[d] - mu) * r * g[d] + be[d];
}

// ---------------- kernel 4: streaming attention ----------------
// grid (T/64, NH, B), block 256; 64q x 64k tiles, no-max softmax (|s|<1)
__global__ void __launch_bounds__(256) attn_kernel(
    const float* __restrict__ Q, const float* __restrict__ K, const float* __restrict__ V,
    const int* __restrict__ qmask, const int* __restrict__ kmask,
    float* __restrict__ Og)
{
    extern __shared__ float sm[];
    float* Qs  = sm;              // [64][68] as [d][q]
    float* KPs = sm + 64 * 68;    // K as [d][k], then P as [q][k]
    float* Vs  = sm + 2 * 64 * 68;// V transposed as [k][d]
    float* kms = sm + 3 * 64 * 68;// [64] key mask

    int b = blockIdx.z, h = blockIdx.y;
    int q0 = blockIdx.x * 64;
    int tid = threadIdx.x;
    int tx = tid & 15, ty = tid >> 4;
    const size_t headoff = (size_t)b * EM * TT + (size_t)h * DH * TT;

    {   // load Q tile -> Qs[d][q]
        int r = tid >> 4, c4 = (tid & 15) * 4;
#pragma unroll
        for (int rr = 0; rr < 64; rr += 16)
            *(float4*)&Qs[(r + rr) * 68 + c4] =
                *(const float4*)(Q + headoff + (size_t)(r + rr) * TT + q0 + c4);
    }

    float accO[4][4] = {};
    float lsum[4] = {};
    const float inv_scale = 1.0f / 181.0f;

    for (int k0 = 0; k0 < TT; k0 += 64) {
        __syncthreads();  // previous iter's reads of KPs/Vs done
        {   // load K -> KPs[d][k], V (transposed) -> Vs[k][d]
            int r = tid >> 4, c4 = (tid & 15) * 4;
#pragma unroll
            for (int rr = 0; rr < 64; rr += 16) {
                *(float4*)&KPs[(r + rr) * 68 + c4] =
                    *(const float4*)(K + headoff + (size_t)(r + rr) * TT + k0 + c4);
                float4 vv = *(const float4*)(V + headoff + (size_t)(r + rr) * TT + k0 + c4);
                Vs[(c4 + 0) * 68 + (r + rr)] = vv.x;
                Vs[(c4 + 1) * 68 + (r + rr)] = vv.y;
                Vs[(c4 + 2) * 68 + (r + rr)] = vv.z;
                Vs[(c4 + 3) * 68 + (r + rr)] = vv.w;
            }
            if (tid < 64) kms[tid] = (float)kmask[b * TT + k0 + tid];
        }
        __syncthreads();

        // S[q][k] = sum_d Qs[d][q] * KPs[d][k]
        float s[4][4] = {};
#pragma unroll
        for (int d = 0; d < 64; d++) {
            float4 a  = *(const float4*)&Qs[d * 68 + ty * 4];
            float4 bv = *(const float4*)&KPs[d * 68 + tx * 4];
            float av[4] = {a.x, a.y, a.z, a.w};
            float bw[4] = {bv.x, bv.y, bv.z, bv.w};
#pragma unroll
            for (int i = 0; i < 4; i++)
#pragma unroll
                for (int j = 0; j < 4; j++) s[i][j] += av[i] * bw[j];
        }

        // p = km ? exp(s/181) : 0  (|s| small -> no max subtraction needed)
        float km[4];
#pragma unroll
        for (int j = 0; j < 4; j++) km[j] = kms[tx * 4 + j];
#pragma unroll
        for (int i = 0; i < 4; i++)
#pragma unroll
            for (int j = 0; j < 4; j++) {
                float p = (km[j] > 0.f) ? __expf(s[i][j] * inv_scale) : 0.f;
                s[i][j] = p;
                lsum[i] += p;
            }

        __syncthreads();  // all S reads of KPs done -> safe to overwrite with P
#pragma unroll
        for (int i = 0; i < 4; i++) {
            float4 pv = make_float4(s[i][0], s[i][1], s[i][2], s[i][3]);
            *(float4*)&KPs[(ty * 4 + i) * 68 + tx * 4] = pv;
        }
        __syncthreads();

        // O[q][d] += sum_k P[q][k] * Vs[k][d]
#pragma unroll
        for (int k = 0; k < 64; k++) {
            float4 vv = *(const float4*)&Vs[k * 68 + tx * 4];
#pragma unroll
            for (int i = 0; i < 4; i++) {
                float p = KPs[(ty * 4 + i) * 68 + k];
                accO[i][0] += p * vv.x;
                accO[i][1] += p * vv.y;
                accO[i][2] += p * vv.z;
                accO[i][3] += p * vv.w;
            }
        }
    }

    // reduce row sums across the 16 tx lanes (within half-warp)
#pragma unroll
    for (int i = 0; i < 4; i++)
#pragma unroll
        for (int off = 8; off > 0; off >>= 1)
            lsum[i] += __shfl_xor_sync(0xffffffffu, lsum[i], off);

    __syncthreads();  // all P@V reads done -> reuse KPs for output staging
#pragma unroll
    for (int i = 0; i < 4; i++) {
        int q = q0 + ty * 4 + i;
        float sc = (qmask[b * TT + q] != 0) ? (1.f / lsum[i]) : 0.f;
#pragma unroll
        for (int j = 0; j < 4; j++)
            KPs[(tx * 4 + j) * 68 + (ty * 4 + i)] = accO[i][j] * sc;  // stage as [d][q]
    }
    __syncthreads();
    {   // coalesced store
        int r = tid >> 4, c4 = (tid & 15) * 4;
#pragma unroll
        for (int rr = 0; rr < 64; rr += 16)
            *(float4*)(Og + headoff + (size_t)(r + rr) * TT + q0 + c4) =
                *(const float4*)&KPs[(r + rr) * 68 + c4];
    }
}

// ---------------- launch ----------------
extern "C" void kernel_launch(void* const* d_in, const int* in_sizes, int n_in,
                              void* d_out, int out_size)
{
    const float* q  = (const float*)d_in[0];
    const float* k  = (const float*)d_in[1];
    const float* v  = (const float*)d_in[2];
    const int* qm   = (const int*)d_in[3];
    const int* km   = (const int*)d_in[4];
    const int* vm   = (const int*)d_in[5];
    const float* Wq = (const float*)d_in[6];
    const float* bq = (const float*)d_in[7];
    const float* Wk = (const float*)d_in[8];
    const float* bk = (const float*)d_in[9];
    const float* Wv = (const float*)d_in[10];
    const float* bv = (const float*)d_in[11];
    const float* Wo = (const float*)d_in[12];
    const float* bo = (const float*)d_in[13];
    const float* gq = (const float*)d_in[14];
    const float* eq = (const float*)d_in[15];
    const float* gk = (const float*)d_in[16];
    const float* ek = (const float*)d_in[17];
    const float* gv = (const float*)d_in[18];
    const float* ev = (const float*)d_in[19];
    float* out = (float*)d_out;

    void *pwn, *pp, *pa;
    cudaGetSymbolAddress(&pwn, g_wn);
    cudaGetSymbolAddress(&pp,  g_p);
    cudaGetSymbolAddress(&pa,  g_attn);
    float* wn0 = (float*)pwn;
    float* wn1 = wn0 + EM * EM;
    float* wn2 = wn1 + EM * EM;
    float* wn3 = wn2 + EM * EM;
    float* p0 = (float*)pp;
    float* p1 = p0 + BB * EM * TT;
    float* p2 = p1 + BB * EM * TT;
    float* ab = (float*)pa;

    // weight standardization
    std_weights<<<EM, 256>>>(Wq, wn0);
    std_weights<<<EM, 256>>>(Wk, wn1);
    std_weights<<<EM, 256>>>(Wv, wn2);
    std_weights<<<EM, 256>>>(Wo, wn3);

    dim3 gp(TT / 64, EM / 64, BB);
    proj64<<<gp, 256>>>(wn0, q, bq, qm, p0);
    proj64<<<gp, 256>>>(wn1, k, bk, km, p1);
    proj64<<<gp, 256>>>(wn2, v, bv, vm, p2);

    dim3 gl(TT / 256, NH, BB);
    ln_head_k<<<gl, 256>>>(p0, gq, eq);
    ln_head_k<<<gl, 256>>>(p1, gk, ek);
    ln_head_k<<<gl, 256>>>(p2, gv, ev);

    int smem = (3 * 64 * 68 + 64) * (int)sizeof(float);
    cudaFuncSetAttribute(attn_kernel, cudaFuncAttributeMaxDynamicSharedMemorySize, smem);
    dim3 ga(TT / 64, NH, BB);
    attn_kernel<<<ga, 256, smem>>>(p0, p1, p2, qm, km, ab);

    proj64<<<gp, 256>>>(wn3, ab, bo, qm, out);
}

// round 6
// speedup vs baseline: 2.4914x; 2.4914x over previous
#include <cuda_runtime.h>
#include <cuda_bf16.h>
#include <cstdint>

#define BB 2
#define EM 512
#define NH 8
#define DH 64
#define TT 2048
#define EPS 1e-5f

// ---------------- scratch ----------------
__device__ __align__(256) __nv_bfloat16 g_WH[4][EM * EM];
__device__ __align__(256) __nv_bfloat16 g_WL[4][EM * EM];
__device__ __align__(256) __nv_bfloat16 g_XH[3][BB * TT * EM];
__device__ __align__(256) __nv_bfloat16 g_XL[3][BB * TT * EM];
__device__ __align__(256) float         g_Yp[BB * EM * TT];
__device__ __align__(256) __nv_bfloat16 g_Qb[BB * NH * TT * DH];
__device__ __align__(256) __nv_bfloat16 g_Kb[BB * NH * TT * DH];
__device__ __align__(256) __nv_bfloat16 g_Vb[BB * NH * DH * TT];
__device__ __align__(256) __nv_bfloat16 g_AoH[BB * TT * EM];
__device__ __align__(256) __nv_bfloat16 g_AoL[BB * TT * EM];
__device__ float g_Sv[BB * NH * DH];
__device__ float g_nv[BB];

// ---------------- helpers ----------------
__device__ __forceinline__ uint32_t smem_u32(const void* p) {
    uint32_t a;
    asm("{ .reg .u64 t; cvta.to.shared.u64 t, %1; cvt.u32.u64 %0, t; }" : "=r"(a) : "l"(p));
    return a;
}

__device__ __forceinline__ void ldm_x4(uint32_t* r, uint32_t a) {
    asm volatile("ldmatrix.sync.aligned.m8n8.x4.shared.b16 {%0,%1,%2,%3}, [%4];"
                 : "=r"(r[0]), "=r"(r[1]), "=r"(r[2]), "=r"(r[3]) : "r"(a));
}

__device__ __forceinline__ void mma16816(float* c, const uint32_t* a, const uint32_t* b) {
    asm volatile(
        "mma.sync.aligned.m16n8k16.row.col.f32.bf16.bf16.f32 "
        "{%0,%1,%2,%3}, {%4,%5,%6,%7}, {%8,%9}, {%0,%1,%2,%3};"
        : "+f"(c[0]), "+f"(c[1]), "+f"(c[2]), "+f"(c[3])
        : "r"(a[0]), "r"(a[1]), "r"(a[2]), "r"(a[3]), "r"(b[0]), "r"(b[1]));
}

// A-operand ldmatrix addr: 16x16 tile at (mo, ko), row-major, stride bytes
__device__ __forceinline__ uint32_t sA_addr(uint32_t base, int stride, int mo, int ko, int lane) {
    int j = lane >> 3, r = lane & 7;
    return base + (uint32_t)((mo + ((j & 1) << 3) + r) * stride + (ko + ((j >> 1) << 3)) * 2);
}
// B-operand (two n-frags) ldmatrix addr: rows = n (K-major storage)
__device__ __forceinline__ uint32_t sB_addr(uint32_t base, int stride, int no, int ko, int lane) {
    int j = lane >> 3, r = lane & 7;
    return base + (uint32_t)((no + ((j >> 1) << 3) + r) * stride + (ko + ((j & 1) << 3)) * 2);
}

__device__ __forceinline__ float expm1p(float s) {
    float p = 1.f / 720.f;
    p = fmaf(p, s, 1.f / 120.f);
    p = fmaf(p, s, 1.f / 24.f);
    p = fmaf(p, s, 1.f / 6.f);
    p = fmaf(p, s, 0.5f);
    p = fmaf(p, s, 1.f);
    return p * s;
}

// ---------------- prep kernels ----------------
__global__ void __launch_bounds__(128) prep_w(const float* __restrict__ W,
                                              __nv_bfloat16* __restrict__ WH,
                                              __nv_bfloat16* __restrict__ WL) {
    __shared__ float red[8];
    int row = blockIdx.x, tid = threadIdx.x;
    const float* wr = W + (size_t)row * EM;
    float s = 0.f, s2 = 0.f;
    for (int i = tid; i < EM; i += 128) { float v = wr[i]; s += v; s2 += v * v; }
    for (int o = 16; o; o >>= 1) { s += __shfl_xor_sync(~0u, s, o); s2 += __shfl_xor_sync(~0u, s2, o); }
    if ((tid & 31) == 0) { red[tid >> 5] = s; red[4 + (tid >> 5)] = s2; }
    __syncthreads();
    s = red[0] + red[1] + red[2] + red[3];
    s2 = red[4] + red[5] + red[6] + red[7];
    float mu = s * (1.f / EM), var = s2 * (1.f / EM) - mu * mu, r = rsqrtf(var + EPS);
    for (int i = tid; i < EM; i += 128) {
        float wn = (wr[i] - mu) * r;
        __nv_bfloat16 h = __float2bfloat16(wn);
        WH[(size_t)row * EM + i] = h;
        WL[(size_t)row * EM + i] = __float2bfloat16(wn - __bfloat162float(h));
    }
}

__global__ void prep_x(const float* __restrict__ X, const int* __restrict__ mask,
                       __nv_bfloat16* __restrict__ XH, __nv_bfloat16* __restrict__ XL) {
    __shared__ float s[32][33];
    int t0 = blockIdx.x * 32, i0 = blockIdx.y * 32, b = blockIdx.z;
    int tx = threadIdx.x, ty = threadIdx.y;
#pragma unroll
    for (int rr = 0; rr < 4; rr++)
        s[ty + 8 * rr][tx] = X[((size_t)b * EM + i0 + ty + 8 * rr) * TT + t0 + tx];
    __syncthreads();
#pragma unroll
    for (int rr = 0; rr < 4; rr++) {
        int tl = ty + 8 * rr, t = t0 + tl;
        float x = s[tx][tl] * (float)mask[b * TT + t];
        __nv_bfloat16 h = __float2bfloat16(x);
        size_t o = ((size_t)b * TT + t) * EM + i0 + tx;
        XH[o] = h;
        XL[o] = __float2bfloat16(x - __bfloat162float(h));
    }
}

__global__ void zero_sv() {
    int i = blockIdx.x * blockDim.x + threadIdx.x;
    if (i < BB * NH * DH) g_Sv[i] = 0.f;
}

__global__ void count_valid(const int* __restrict__ km) {
    __shared__ float red[8];
    int b = blockIdx.x, tid = threadIdx.x;
    float c = 0.f;
    for (int t = tid; t < TT; t += 256) c += (float)km[b * TT + t];
    for (int o = 16; o; o >>= 1) c += __shfl_xor_sync(~0u, c, o);
    if ((tid & 31) == 0) red[tid >> 5] = c;
    __syncthreads();
    if (tid == 0) {
        float tt = 0.f;
        for (int w = 0; w < 8; w++) tt += red[w];
        g_nv[b] = tt;
    }
}

// ---------------- projection GEMM (mma.sync bf16 split-3) ----------------
// Y[b][m][t] = Wn[m][i] @ X[t][i] + bias[m];  tiles 128x128, K chunks of 64
__global__ void __launch_bounds__(256) proj_wmma(
    const __nv_bfloat16* __restrict__ AH, const __nv_bfloat16* __restrict__ AL,
    const __nv_bfloat16* __restrict__ BH, const __nv_bfloat16* __restrict__ BL,
    const float* __restrict__ bias, float* __restrict__ Y)
{
    extern __shared__ __align__(16) char smc[];
    __nv_bfloat16* sAh = (__nv_bfloat16*)smc;      // [128][72]
    __nv_bfloat16* sAl = sAh + 128 * 72;
    __nv_bfloat16* sBh = sAl + 128 * 72;
    __nv_bfloat16* sBl = sBh + 128 * 72;
    uint32_t bAh = smem_u32(sAh), bAl = smem_u32(sAl);
    uint32_t bBh = smem_u32(sBh), bBl = smem_u32(sBl);
    int tid = threadIdx.x, lane = tid & 31, wid = tid >> 5;
    int wm = wid >> 2, wn = wid & 3;
    int t0 = blockIdx.x * 128, m0 = blockIdx.y * 128, b = blockIdx.z;
    const __nv_bfloat16* gAh = AH + (size_t)m0 * EM;
    const __nv_bfloat16* gAl = AL + (size_t)m0 * EM;
    const __nv_bfloat16* gBh = BH + ((size_t)b * TT + t0) * EM;
    const __nv_bfloat16* gBl = BL + ((size_t)b * TT + t0) * EM;

    float acc[4][4][4] = {};

    for (int kc = 0; kc < 8; kc++) {
        int k0 = kc * 64;
        __syncthreads();
        for (int idx = tid; idx < 1024; idx += 256) {
            int r = idx >> 3, j = idx & 7;
            *(uint4*)(sAh + r * 72 + j * 8) = *(const uint4*)(gAh + (size_t)r * EM + k0 + j * 8);
            *(uint4*)(sAl + r * 72 + j * 8) = *(const uint4*)(gAl + (size_t)r * EM + k0 + j * 8);
            *(uint4*)(sBh + r * 72 + j * 8) = *(const uint4*)(gBh + (size_t)r * EM + k0 + j * 8);
            *(uint4*)(sBl + r * 72 + j * 8) = *(const uint4*)(gBl + (size_t)r * EM + k0 + j * 8);
        }
        __syncthreads();
#pragma unroll
        for (int ks = 0; ks < 4; ks++) {
            uint32_t ah[4][4], al[4][4], bh[2][4], bl[2][4];
#pragma unroll
            for (int mf = 0; mf < 4; mf++) {
                ldm_x4(ah[mf], sA_addr(bAh, 144, wm * 64 + mf * 16, ks * 16, lane));
                ldm_x4(al[mf], sA_addr(bAl, 144, wm * 64 + mf * 16, ks * 16, lane));
            }
#pragma unroll
            for (int np = 0; np < 2; np++) {
                ldm_x4(bh[np], sB_addr(bBh, 144, wn * 32 + np * 16, ks * 16, lane));
                ldm_x4(bl[np], sB_addr(bBl, 144, wn * 32 + np * 16, ks * 16, lane));
            }
#pragma unroll
            for (int mf = 0; mf < 4; mf++)
#pragma unroll
                for (int nf = 0; nf < 4; nf++) {
                    const uint32_t* ph = &bh[nf >> 1][(nf & 1) * 2];
                    const uint32_t* pl = &bl[nf >> 1][(nf & 1) * 2];
                    mma16816(acc[mf][nf], ah[mf], ph);
                    mma16816(acc[mf][nf], ah[mf], pl);
                    mma16816(acc[mf][nf], al[mf], ph);
                }
        }
    }
#pragma unroll
    for (int mf = 0; mf < 4; mf++)
#pragma unroll
        for (int rr = 0; rr < 2; rr++) {
            int m = m0 + wm * 64 + mf * 16 + (lane >> 2) + rr * 8;
            float bi = bias[m];
            float* yo = Y + ((size_t)b * EM + m) * TT + t0 + wn * 32;
#pragma unroll
            for (int nf = 0; nf < 4; nf++) {
                float2 v = make_float2(acc[mf][nf][rr * 2] + bi, acc[mf][nf][rr * 2 + 1] + bi);
                *(float2*)(yo + nf * 8 + 2 * (lane & 3)) = v;
            }
        }
}

// ---------------- per-head LN + emit bf16 ----------------
__global__ void __launch_bounds__(256) ln_emit(
    const float* __restrict__ Y, const float* __restrict__ g, const float* __restrict__ be,
    __nv_bfloat16* __restrict__ oTD, __nv_bfloat16* __restrict__ oDT,
    const int* __restrict__ km, int mode) {
    __shared__ float sacc[64];
    int t = blockIdx.x * 256 + threadIdx.x, h = blockIdx.y, b = blockIdx.z;
    const float* base = Y + ((size_t)b * EM + h * 64) * TT + t;
    float v[64];
    float s = 0.f, s2 = 0.f;
#pragma unroll
    for (int d = 0; d < 64; d++) { v[d] = base[(size_t)d * TT]; s += v[d]; s2 += v[d] * v[d]; }
    float mu = s * (1.f / 64), var = s2 * (1.f / 64) - mu * mu, rs = rsqrtf(var + EPS);
#pragma unroll
    for (int d = 0; d < 64; d++) v[d] = (v[d] - mu) * rs * g[d] + be[d];
    if (mode == 0) {
        __nv_bfloat16* o = oTD + (((size_t)b * NH + h) * TT + t) * 64;
#pragma unroll
        for (int dd = 0; dd < 64; dd += 8) {
            uint32_t pk[4];
#pragma unroll
            for (int e = 0; e < 4; e++) {
                __nv_bfloat162 p = __floats2bfloat162_rn(v[dd + 2 * e], v[dd + 2 * e + 1]);
                pk[e] = *(uint32_t*)&p;
            }
            *(uint4*)(o + dd) = *(uint4*)pk;
        }
    } else {
        __nv_bfloat16* o = oDT + ((size_t)b * NH + h) * (size_t)(64 * TT) + t;
#pragma unroll
        for (int d = 0; d < 64; d++) o[(size_t)d * TT] = __float2bfloat16(v[d]);
        if (threadIdx.x < 64) sacc[threadIdx.x] = 0.f;
        __syncthreads();
        float w = (float)km[b * TT + t];
#pragma unroll
        for (int d = 0; d < 64; d++) {
            float x = v[d] * w;
            for (int off = 16; off; off >>= 1) x += __shfl_xor_sync(~0u, x, off);
            if ((threadIdx.x & 31) == 0) atomicAdd(&sacc[d], x);
        }
        __syncthreads();
        if (threadIdx.x < 64) atomicAdd(&g_Sv[((size_t)b * NH + h) * 64 + threadIdx.x], sacc[threadIdx.x]);
    }
}

// ---------------- fused attention (mma.sync) ----------------
// block: 128 q rows x full K loop; 8 warps = 2(q) x 4(k/d)
__global__ void __launch_bounds__(256) attn_wmma(const int* __restrict__ qmask,
                                                 const int* __restrict__ kmask)
{
    extern __shared__ __align__(16) char smc[];
    __nv_bfloat16* sQ = (__nv_bfloat16*)smc;       // [128][72]
    __nv_bfloat16* sK = sQ + 128 * 72;             // [128][72]
    __nv_bfloat16* sV = sK + 128 * 72;             // [64][136]  (rows d, K-major over k)
    __nv_bfloat16* sU = sV + 64 * 136;             // [128][136] (rows q, K-major over k)
    float* kms = (float*)(sU + 128 * 136);         // [128]
    float* rs = kms + 128;                         // [128]
    uint32_t aQ = smem_u32(sQ), aK = smem_u32(sK), aV = smem_u32(sV), aU = smem_u32(sU);
    int tid = threadIdx.x, lane = tid & 31, wid = tid >> 5;
    int wm = wid >> 2, wn = wid & 3;
    int q0 = blockIdx.x * 128;
    int b = blockIdx.y >> 3, h = blockIdx.y & 7;
    size_t hb = (size_t)(b * NH + h);
    const __nv_bfloat16* gQ = g_Qb + (hb * TT + q0) * 64;
    const __nv_bfloat16* gK = g_Kb + hb * TT * 64;
    const __nv_bfloat16* gV = g_Vb + hb * (size_t)(64 * TT);

    for (int idx = tid; idx < 1024; idx += 256) {
        int r = idx >> 3, j = idx & 7;
        *(uint4*)(sQ + r * 72 + j * 8) = *(const uint4*)(gQ + (size_t)r * 64 + j * 8);
    }
    if (tid < 128) rs[tid] = 0.f;

    float oc[4][2][4] = {};
    float rsum[4][2] = {};
    const float inv181 = 1.f / 181.f;

    for (int kc = 0; kc < 16; kc++) {
        int k0 = kc * 128;
        __syncthreads();
        for (int idx = tid; idx < 1024; idx += 256) {
            int r = idx >> 3, j = idx & 7;
            *(uint4*)(sK + r * 72 + j * 8) = *(const uint4*)(gK + (size_t)(k0 + r) * 64 + j * 8);
        }
        for (int idx = tid; idx < 1024; idx += 256) {
            int r = idx >> 4, j = idx & 15;
            *(uint4*)(sV + r * 136 + j * 8) = *(const uint4*)(gV + (size_t)r * TT + k0 + j * 8);
        }
        if (tid < 128) kms[tid] = (float)kmask[b * TT + k0 + tid];
        __syncthreads();

        // S = Q @ K^T  (64q x 32k per warp)
        float sc[4][4][4] = {};
#pragma unroll
        for (int ks = 0; ks < 4; ks++) {
            uint32_t aq[4][4], bk[2][4];
#pragma unroll
            for (int mf = 0; mf < 4; mf++)
                ldm_x4(aq[mf], sA_addr(aQ, 144, wm * 64 + mf * 16, ks * 16, lane));
#pragma unroll
            for (int np = 0; np < 2; np++)
                ldm_x4(bk[np], sB_addr(aK, 144, wn * 32 + np * 16, ks * 16, lane));
#pragma unroll
            for (int mf = 0; mf < 4; mf++)
#pragma unroll
                for (int nf = 0; nf < 4; nf++)
                    mma16816(sc[mf][nf], aq[mf], &bk[nf >> 1][(nf & 1) * 2]);
        }

        // u = km * expm1(s/181), store bf16 to sU, accumulate rowsums
#pragma unroll
        for (int mf = 0; mf < 4; mf++) {
            int r0 = wm * 64 + mf * 16 + (lane >> 2);
#pragma unroll
            for (int nf = 0; nf < 4; nf++) {
                int c0 = wn * 32 + nf * 8 + 2 * (lane & 3);
                float k0f = kms[c0], k1f = kms[c0 + 1];
                float u00 = expm1p(sc[mf][nf][0] * inv181) * k0f;
                float u01 = expm1p(sc[mf][nf][1] * inv181) * k1f;
                float u10 = expm1p(sc[mf][nf][2] * inv181) * k0f;
                float u11 = expm1p(sc[mf][nf][3] * inv181) * k1f;
                rsum[mf][0] += u00 + u01;
                rsum[mf][1] += u10 + u11;
                __nv_bfloat162 p0 = __floats2bfloat162_rn(u00, u01);
                __nv_bfloat162 p1 = __floats2bfloat162_rn(u10, u11);
                *(uint32_t*)((char*)sU + r0 * 272 + c0 * 2) = *(uint32_t*)&p0;
                *(uint32_t*)((char*)sU + (r0 + 8) * 272 + c0 * 2) = *(uint32_t*)&p1;
            }
        }
        __syncthreads();

        // O += U @ V^T  (64q x 16d per warp, contraction over 128 k)
#pragma unroll
        for (int kk = 0; kk < 8; kk++) {
            uint32_t au[4][4], bv[4];
#pragma unroll
            for (int mf = 0; mf < 4; mf++)
                ldm_x4(au[mf], sA_addr(aU, 272, wm * 64 + mf * 16, kk * 16, lane));
            ldm_x4(bv, sB_addr(aV, 272, wn * 16, kk * 16, lane));
#pragma unroll
            for (int mf = 0; mf < 4; mf++) {
                mma16816(oc[mf][0], au[mf], &bv[0]);
                mma16816(oc[mf][1], au[mf], &bv[2]);
            }
        }
    }
    __syncthreads();

    // reduce rowsums: quad shuffle then atomic into smem
#pragma unroll
    for (int mf = 0; mf < 4; mf++)
#pragma unroll
        for (int ul = 0; ul < 2; ul++) {
            float v = rsum[mf][ul];
            v += __shfl_xor_sync(~0u, v, 1);
            v += __shfl_xor_sync(~0u, v, 2);
            if ((lane & 3) == 0)
                atomicAdd(&rs[wm * 64 + mf * 16 + (lane >> 2) + ul * 8], v);
        }
    __syncthreads();

    float nv = g_nv[b];
    const float* sv = g_Sv + hb * 64;
#pragma unroll
    for (int mf = 0; mf < 4; mf++)
#pragma unroll
        for (int rr = 0; rr < 2; rr++) {
            int row = wm * 64 + mf * 16 + (lane >> 2) + rr * 8;
            int q = q0 + row;
            float l = nv + rs[row];
            float inv = (qmask[b * TT + q] != 0) ? (1.f / l) : 0.f;
            __nv_bfloat16* oH = g_AoH + ((size_t)b * TT + q) * EM + h * 64;
            __nv_bfloat16* oL = g_AoL + ((size_t)b * TT + q) * EM + h * 64;
#pragma unroll
            for (int nf = 0; nf < 2; nf++) {
                int d0 = wn * 16 + nf * 8 + 2 * (lane & 3);
                float x0 = (oc[mf][nf][rr * 2] + sv[d0]) * inv;
                float x1 = (oc[mf][nf][rr * 2 + 1] + sv[d0 + 1]) * inv;
                __nv_bfloat16 h0 = __float2bfloat16(x0), h1 = __float2bfloat16(x1);
                __nv_bfloat162 ph = __halves2bfloat162(h0, h1);
                __nv_bfloat162 pl = __floats2bfloat162_rn(x0 - __bfloat162float(h0),
                                                          x1 - __bfloat162float(h1));
                *(uint32_t*)(oH + d0) = *(uint32_t*)&ph;
                *(uint32_t*)(oL + d0) = *(uint32_t*)&pl;
            }
        }
}

// ---------------- launch ----------------
extern "C" void kernel_launch(void* const* d_in, const int* in_sizes, int n_in,
                              void* d_out, int out_size) {
    const float* q  = (const float*)d_in[0];
    const float* k  = (const float*)d_in[1];
    const float* v  = (const float*)d_in[2];
    const int* qm   = (const int*)d_in[3];
    const int* km   = (const int*)d_in[4];
    const int* vm   = (const int*)d_in[5];
    const float* W[4]  = {(const float*)d_in[6], (const float*)d_in[8], (const float*)d_in[10], (const float*)d_in[12]};
    const float* bi[4] = {(const float*)d_in[7], (const float*)d_in[9], (const float*)d_in[11], (const float*)d_in[13]};
    const float* lng[3] = {(const float*)d_in[14], (const float*)d_in[16], (const float*)d_in[18]};
    const float* lnb[3] = {(const float*)d_in[15], (const float*)d_in[17], (const float*)d_in[19]};
    float* out = (float*)d_out;

    void *pWH, *pWL, *pXH, *pXL, *pY, *pQ, *pK, *pV, *pAH, *pAL;
    cudaGetSymbolAddress(&pWH, g_WH); cudaGetSymbolAddress(&pWL, g_WL);
    cudaGetSymbolAddress(&pXH, g_XH); cudaGetSymbolAddress(&pXL, g_XL);
    cudaGetSymbolAddress(&pY, g_Yp);
    cudaGetSymbolAddress(&pQ, g_Qb); cudaGetSymbolAddress(&pK, g_Kb); cudaGetSymbolAddress(&pV, g_Vb);
    cudaGetSymbolAddress(&pAH, g_AoH); cudaGetSymbolAddress(&pAL, g_AoL);
    __nv_bfloat16* WH = (__nv_bfloat16*)pWH;
    __nv_bfloat16* WL = (__nv_bfloat16*)pWL;
    __nv_bfloat16* XH = (__nv_bfloat16*)pXH;
    __nv_bfloat16* XL = (__nv_bfloat16*)pXL;
    float* Yp = (float*)pY;

    const int PROJ_SMEM = 4 * 128 * 72 * 2;                       // 73728
    const int ATTN_SMEM = (2 * 128 * 72 + 64 * 136 + 128 * 136) * 2 + 2 * 128 * 4;  // 90112
    cudaFuncSetAttribute(proj_wmma, cudaFuncAttributeMaxDynamicSharedMemorySize, PROJ_SMEM);
    cudaFuncSetAttribute(attn_wmma, cudaFuncAttributeMaxDynamicSharedMemorySize, ATTN_SMEM);

    for (int i = 0; i < 4; i++)
        prep_w<<<EM, 128>>>(W[i], WH + (size_t)i * EM * EM, WL + (size_t)i * EM * EM);

    const float* xin[3] = {q, k, v};
    const int* msk[3] = {qm, km, vm};
    dim3 gx(TT / 32, EM / 32, BB);
    for (int i = 0; i < 3; i++)
        prep_x<<<gx, dim3(32, 8)>>>(xin[i], msk[i],
                                    XH + (size_t)i * BB * TT * EM, XL + (size_t)i * BB * TT * EM);
    zero_sv<<<(BB * NH * DH + 255) / 256, 256>>>();
    count_valid<<<BB, 256>>>(km);

    dim3 gp(TT / 128, EM / 128, BB);
    dim3 gl(TT / 256, NH, BB);
    for (int i = 0; i < 3; i++) {
        proj_wmma<<<gp, 256, PROJ_SMEM>>>(WH + (size_t)i * EM * EM, WL + (size_t)i * EM * EM,
                                          XH + (size_t)i * BB * TT * EM, XL + (size_t)i * BB * TT * EM,
                                          bi[i], Yp);
        if (i == 0)      ln_emit<<<gl, 256>>>(Yp, lng[0], lnb[0], (__nv_bfloat16*)pQ, nullptr, km, 0);
        else if (i == 1) ln_emit<<<gl, 256>>>(Yp, lng[1], lnb[1], (__nv_bfloat16*)pK, nullptr, km, 0);
        else             ln_emit<<<gl, 256>>>(Yp, lng[2], lnb[2], nullptr, (__nv_bfloat16*)pV, km, 1);
    }

    attn_wmma<<<dim3(TT / 128, BB * NH), 256, ATTN_SMEM>>>(qm, km);

    proj_wmma<<<gp, 256, PROJ_SMEM>>>(WH + (size_t)3 * EM * EM, WL + (size_t)3 * EM * EM,
                                      (__nv_bfloat16*)pAH, (__nv_bfloat16*)pAL, bi[3], out);
}